// round 2
// baseline (speedup 1.0000x reference)
#include <cuda_runtime.h>

// out[n,p,d] = feat[n,p,d] * mean_m(task[n,m,p])
// n=32, m=16, p=1024, d=512  (fixed by the problem's setup_inputs)

static constexpr int N = 32;
static constexpr int M = 16;
static constexpr int P = 1024;
static constexpr int D = 512;

__global__ void __launch_bounds__(128) map_scale_kernel(
    const float* __restrict__ task,   // [N, M, P]
    const float* __restrict__ feat,   // [N, P, D]
    float* __restrict__ out)          // [N, P, D]
{
    const int np = blockIdx.x;        // 0 .. N*P-1
    const int n  = np >> 10;          // P = 1024
    const int p  = np & (P - 1);

    // Mean over m: 16 loads, stride P floats. Same addresses for all lanes
    // in the warp -> broadcast (no extra traffic after first warp).
    const float* t = task + (size_t)n * M * P + p;
    float s = 0.0f;
#pragma unroll
    for (int m = 0; m < M; ++m) s += t[(size_t)m * P];
    const float mean = s * (1.0f / (float)M);

    // D = 512 floats = 128 float4 -> exactly one float4 per thread.
    const float4* f = reinterpret_cast<const float4*>(feat + (size_t)np * D);
    float4*       o = reinterpret_cast<float4*>(out + (size_t)np * D);

    float4 v = f[threadIdx.x];
    v.x *= mean; v.y *= mean; v.z *= mean; v.w *= mean;
    o[threadIdx.x] = v;
}

extern "C" void kernel_launch(void* const* d_in, const int* in_sizes, int n_in,
                              void* d_out, int out_size)
{
    const float* task = (const float*)d_in[0];   // [N, M, P]
    const float* feat = (const float*)d_in[1];   // [N, P, D]
    float* out = (float*)d_out;                  // [N, P, D]

    map_scale_kernel<<<N * P, 128>>>(task, feat, out);
}

// round 3
// speedup vs baseline: 1.2439x; 1.2439x over previous
#include <cuda_runtime.h>

// out[n,p,d] = feat[n,p,d] * mean_m(task[n,m,p])
// n=32, m=16, p=1024, d=512

static constexpr int N = 32;
static constexpr int M = 16;
static constexpr int P = 1024;
static constexpr int D = 512;
static constexpr int NP = N * P;                 // 32768 rows
static constexpr int D4 = D / 4;                 // 128 float4 per row
static constexpr long long TOTAL4 = (long long)NP * D4;  // 4,194,304 float4

// Scratch for row means (no cudaMalloc allowed).
__device__ float g_mean[NP];

// ---------------------------------------------------------------------------
// Kernel 1: mean over m for each (n,p). 32768 outputs; 2 MB read.
// Thread t handles one (n,p). Consecutive threads -> consecutive p ->
// coalesced loads for each m; the m-loop is unrolled so the 16 loads are
// independent (MLP=16).
// ---------------------------------------------------------------------------
__global__ void __launch_bounds__(256) mean_kernel(const float* __restrict__ task)
{
    const int np = blockIdx.x * 256 + threadIdx.x;   // 0..NP-1
    const int n  = np >> 10;
    const int p  = np & (P - 1);

    const float* t = task + (size_t)n * M * P + p;
    float s = 0.0f;
#pragma unroll
    for (int m = 0; m < M; ++m) s += t[(size_t)m * P];
    g_mean[np] = s * (1.0f / (float)M);
}

// ---------------------------------------------------------------------------
// Kernel 2: pure streaming multiply. Each thread handles U=4 independent
// float4 elements (front-batched loads -> MLP>=4 on the bulk stream).
// mean loads hit L1/L2 (128 KB table, broadcast within row segments).
// ---------------------------------------------------------------------------
static constexpr int U = 4;
static constexpr int TPB = 256;
static constexpr int GRID2 = (int)(TOTAL4 / (TPB * U));   // 4096 blocks

__global__ void __launch_bounds__(TPB) scale_kernel(
    const float* __restrict__ feat,   // [NP, D]
    float* __restrict__ out)          // [NP, D]
{
    const long long base = (long long)blockIdx.x * (TPB * U) + threadIdx.x;

    const float4* f = reinterpret_cast<const float4*>(feat);
    float4*       o = reinterpret_cast<float4*>(out);

    long long idx[U];
    float4 v[U];
    float  mn[U];

#pragma unroll
    for (int k = 0; k < U; ++k) {
        idx[k] = base + (long long)k * TPB;
        v[k]   = f[idx[k]];                         // independent LDG.128 x4
    }
#pragma unroll
    for (int k = 0; k < U; ++k) {
        mn[k] = __ldg(&g_mean[idx[k] >> 7]);        // row = idx / D4, cached
    }
#pragma unroll
    for (int k = 0; k < U; ++k) {
        v[k].x *= mn[k]; v[k].y *= mn[k];
        v[k].z *= mn[k]; v[k].w *= mn[k];
        o[idx[k]] = v[k];
    }
}

extern "C" void kernel_launch(void* const* d_in, const int* in_sizes, int n_in,
                              void* d_out, int out_size)
{
    const float* task = (const float*)d_in[0];   // [N, M, P]
    const float* feat = (const float*)d_in[1];   // [N, P, D]
    float* out = (float*)d_out;

    mean_kernel<<<NP / 256, 256>>>(task);
    scale_kernel<<<GRID2, TPB>>>(feat, out);
}